// round 12
// baseline (speedup 1.0000x reference)
#include <cuda_runtime.h>
#include <cuda_bf16.h>
#include <cstdint>

// Output pattern, shape [2, G*N*N] flattened row-major, FLOAT32 values:
//   half 0: out[g*N*N + i]     = float(i / N)   (row index)
//   half 1: out[H + g*N*N + i] = float(i % N)   (col index),  H = G*N*N
// Pure write-only stream (512 MiB for N=4096, G=4); inputs' values unused.
//
// Measured design space (R3-R11):
//  - (R4)  per-instruction warp footprint = contiguous fully-covered 2KB span
//          (thread = one float4/STG); wider contiguous per-thread tiling ->
//          L2/HBM read-modify-write, 2x time.
//  - (R8)  persistent grid regresses (+9%): serialized units lower store
//          pressure vs fresh small CTAs.
//  - (R10) one-shot stores (1024t, no loop) regress (+22%): prologue
//          amortized over 16B/thread -> ALU/issue-bound.
//  - (R5-R11) HBM write-stream ceiling ~7.45 TB/s (~83-84% DRAM active);
//          2KB-grain L2 hash neutralizes locality beyond the warp span.
//  - R12: compile-time ITERS so ptxas unrolls the row loop into 4
//          back-to-back STG.128 with immediate offsets (front-batched store
//          MLP, less ALU). Layout identical to R9.

template <int ITERS>
__global__ void fa_row_split_kernel_t(float* __restrict__ out,
                                      unsigned N, unsigned G,
                                      long long halfElems) {
    const unsigned r = blockIdx.y;                 // row index
    const unsigned z = blockIdx.z;
    const bool colHalf = (z >= G);
    const unsigned g = colHalf ? (z - G) : z;
    const long long NNll = (long long)N * (long long)N;

    const long long base = (colHalf ? halfElems : 0LL)
                         + (long long)g * NNll
                         + (long long)r * (long long)N
                         + (long long)(threadIdx.x * 4u);

    const unsigned stride = blockDim.x * 4u;       // 1024 floats

    if (colHalf) {
        const float c0 = (float)(threadIdx.x * 4u);
#pragma unroll
        for (int j = 0; j < ITERS; j++) {
            float c = c0 + (float)(j * 1024);      // stride==1024 on this path
            __stcs(reinterpret_cast<float4*>(out + base + (long long)j * stride),
                   make_float4(c, c + 1.0f, c + 2.0f, c + 3.0f));
        }
    } else {
        const float rf = (float)r;
        const float4 rv = make_float4(rf, rf, rf, rf);
#pragma unroll
        for (int j = 0; j < ITERS; j++) {
            __stcs(reinterpret_cast<float4*>(out + base + (long long)j * stride),
                   rv);
        }
    }
}

// Runtime-iters variant for N multiples of 1024 other than 4096.
__global__ void fa_row_split_kernel(float* __restrict__ out,
                                    unsigned N, unsigned G,
                                    long long halfElems) {
    const unsigned r = blockIdx.y;
    const unsigned z = blockIdx.z;
    const bool colHalf = (z >= G);
    const unsigned g = colHalf ? (z - G) : z;
    const long long NNll = (long long)N * (long long)N;

    long long base = (colHalf ? halfElems : 0LL)
                   + (long long)g * NNll
                   + (long long)r * (long long)N
                   + (long long)(threadIdx.x * 4u);

    const unsigned stride = blockDim.x * 4u;
    const unsigned iters = N / stride;

    if (colHalf) {
        float c = (float)(threadIdx.x * 4u);
        for (unsigned j = 0; j < iters; j++) {
            __stcs(reinterpret_cast<float4*>(out + base),
                   make_float4(c, c + 1.0f, c + 2.0f, c + 3.0f));
            base += stride;
            c += (float)stride;
        }
    } else {
        const float rf = (float)r;
        const float4 rv = make_float4(rf, rf, rf, rf);
        for (unsigned j = 0; j < iters; j++) {
            __stcs(reinterpret_cast<float4*>(out + base), rv);
            base += stride;
        }
    }
}

// Generic path: thread = one float4 per half, N % 4 == 0.
__global__ void fa_vec_kernel(float* __restrict__ out,
                              unsigned N, unsigned NN, long long halfElems) {
    unsigned i4 = ((unsigned)blockIdx.x * blockDim.x + threadIdx.x) * 4u;
    if (i4 >= NN) return;
    unsigned r = i4 / N;
    unsigned c = i4 - r * N;
    long long base = (long long)blockIdx.y * (long long)NN + (long long)i4;
    float rf = (float)r, cf = (float)c;
    __stcs(reinterpret_cast<float4*>(out + base),
           make_float4(rf, rf, rf, rf));
    __stcs(reinterpret_cast<float4*>(out + halfElems + base),
           make_float4(cf, cf + 1.0f, cf + 2.0f, cf + 3.0f));
}

// Scalar fallback.
__global__ void fa_scalar_kernel(float* __restrict__ out,
                                 unsigned N, unsigned NN, long long halfElems) {
    unsigned i = (unsigned)blockIdx.x * blockDim.x + threadIdx.x;
    if (i >= NN) return;
    unsigned r = i / N;
    unsigned c = i - r * N;
    long long base = (long long)blockIdx.y * (long long)NN + (long long)i;
    out[base] = (float)r;
    out[halfElems + base] = (float)c;
}

extern "C" void kernel_launch(void* const* d_in, const int* in_sizes, int n_in,
                              void* d_out, int out_size) {
    (void)d_in;
    // Derive N: the input size s with out_size == 2*G*s*s, integer 1<=G<=4096.
    long long N = 0, G = 0;
    for (int i = 0; i < n_in; i++) {
        long long s = (long long)in_sizes[i];
        if (s <= 0) continue;
        long long denom = 2LL * s * s;
        if (denom <= 0) continue;
        if ((long long)out_size % denom != 0) continue;
        long long g = (long long)out_size / denom;
        if (g >= 1 && g <= 4096) { N = s; G = g; break; }
    }
    if (N == 0) {
        N = (long long)in_sizes[2];
        long long denom = 2LL * N * N;
        G = (denom > 0 && (long long)out_size % denom == 0)
                ? (long long)out_size / denom : 1;
    }

    const long long NNll = N * N;
    const unsigned NN = (unsigned)NNll;
    const long long halfElems = G * NNll;
    float* out = (float*)d_out;
    const int threads = 256;

    if (N == 4096 && 2 * G <= 65535LL) {
        // Compile-time ITERS=4: ptxas unrolls into 4 back-to-back STG.128.
        dim3 grid(1, (unsigned)N, (unsigned)(2 * G));
        fa_row_split_kernel_t<4><<<grid, threads>>>(out, (unsigned)N,
                                                    (unsigned)G, halfElems);
    } else if ((N % (threads * 4)) == 0 && N <= 65535LL && 2 * G <= 65535LL) {
        dim3 grid(1, (unsigned)N, (unsigned)(2 * G));
        fa_row_split_kernel<<<grid, threads>>>(out, (unsigned)N, (unsigned)G,
                                               halfElems);
    } else if ((N % 4) == 0 && NNll <= 0xFFFFFFFFLL) {
        const unsigned elems4 = NN / 4u;
        unsigned gx = (elems4 + threads - 1) / threads;
        if (gx == 0) gx = 1;
        dim3 grid(gx, (unsigned)G, 1);
        fa_vec_kernel<<<grid, threads>>>(out, (unsigned)N, NN, halfElems);
    } else {
        unsigned gx = (unsigned)((NNll + threads - 1) / threads);
        if (gx == 0) gx = 1;
        dim3 grid(gx, (unsigned)G, 1);
        fa_scalar_kernel<<<grid, threads>>>(out, (unsigned)N, NN, halfElems);
    }
}